// round 14
// baseline (speedup 1.0000x reference)
#include <cuda_runtime.h>

#define GN 4096   // N*N
#define TT 168    // T
#define BB 128    // B
#define NN 64     // N
#define PP 128    // P

#define Y_BLOCKS   32                 // 4 batches each
#define YB_BATCH   4
#define MV_BLOCKS  (GN / NN)          // 64 rows (one full i-group) per block -> 64? no:
// one i-group = 64 rows; MV block handles one i-group => 64 blocks? We need
// 128 SM coverage; use 128 MV blocks? i in [0,64): 64 groups. 64 blocks is
// too few SMs. Instead: one block per i-group BUT two i-groups per... keep
// 64 groups, 2 blocks would split v. Decision: 128 MV blocks, each handles
// HALF the rows of... no — v must be block-local. Final: 64 MV blocks of
// 512 threads (16 warps, 4 rows/warp) + 32 y-blocks of 512 threads.
#undef MV_BLOCKS
#define MV_BLOCKS  64
#define THREADS    512
#define TOTAL_BLK  (Y_BLOCKS + MV_BLOCKS)   // 96 blocks, single wave

// Scratch + sync (allocation-free rule: __device__ globals; zero at load,
// self-resetting every replay)
__device__ float d_y[BB * NN];
__device__ int   d_y_done;
__device__ int   d_mv_done;

__device__ __forceinline__ float dot4(float4 a, float4 b) {
    return a.x * b.x + a.y * b.y + a.z * b.z + a.w * b.w;
}

__device__ __forceinline__ int ld_flag(const int* p) {
    int v;
    asm volatile("ld.global.cg.b32 %0, [%1];" : "=r"(v) : "l"(p) : "memory");
    return v;
}

// ---------------------------------------------------------------------------
// ONE kernel, 96 blocks x 512 threads (single wave; every SM gets work since
// 96 blocks x 16 warps = 1536 warps spread by the scheduler):
//  blocks [0, 32):  y for 4 batches: y[b,j] = sum_p x[b,j,p]*alpha[xi[b,p]];
//                   fence; signal y_done. Done ~2us in.
//  blocks [32, 96): i-group block: rows gi*64..gi*64+63 (gi = blk-32).
//                   w^2 in smem, 16 warps x 4 rows each, fused F epilogue,
//                   v kept in SMEM. Then gate y_done==32 (passes instantly,
//                   y finished ~6us earlier) and compute the full Z column:
//                   Z[b, gi] = sum_j v[j] * y[b,j]  — plain stores, one
//                   thread per (b, half), no atomics, no zeroing.
// ---------------------------------------------------------------------------
__global__ void __launch_bounds__(THREADS) k_all(const float* __restrict__ g,
                                                 const float* __restrict__ w,
                                                 const float* __restrict__ alphas,
                                                 const float* __restrict__ x,
                                                 const int*   __restrict__ xi,
                                                 float* __restrict__ Fout,
                                                 float* __restrict__ Zout) {
    __shared__ __align__(16) float ws[GN];       // mv: w^2 | y: ap
    __shared__ __align__(16) float sal[TT + 8];
    __shared__ __align__(16) float sv[NN];       // this block's v slice

    const int blk  = blockIdx.x;
    const int tid  = threadIdx.x;
    const int wid  = tid >> 5;
    const int lane = tid & 31;

    if (blk < Y_BLOCKS) {
        // ---------------- y-block: batches b0..b0+3 ----------------
        const int b0 = blk * YB_BATCH;
        float* ap = ws;                      // 4 x 128 = 512 entries
        ap[tid] = alphas[xi[b0 * PP + tid]];
        __syncthreads();

        const int bsel = wid >> 2;           // 0..3
        const int b    = b0 + bsel;
        const int j0   = wid & 3;
        const float* __restrict__ apb = ap + bsel * PP;
        #pragma unroll
        for (int j = j0; j < NN; j += 4) {
            const float* __restrict__ xr = x + ((size_t)b * NN + j) * PP;
            float s = xr[lane]      * apb[lane]
                    + xr[lane + 32] * apb[lane + 32]
                    + xr[lane + 64] * apb[lane + 64]
                    + xr[lane + 96] * apb[lane + 96];
            #pragma unroll
            for (int o = 16; o > 0; o >>= 1)
                s += __shfl_xor_sync(0xffffffffu, s, o);
            if (lane == 0) d_y[b * NN + j] = s;
        }
        __syncthreads();
        if (tid == 0) {
            __threadfence();
            atomicAdd(&d_y_done, 1);
        }
        return;
    }

    // ---------------- i-group matvec block ----------------
    const int gi = blk - Y_BLOCKS;           // 0..63; rows gi*64 .. gi*64+63

    // stage w^2 (16 KB) + alphas into smem
    const float4* __restrict__ w4g = reinterpret_cast<const float4*>(w);
    float4* ws4 = reinterpret_cast<float4*>(ws);
    #pragma unroll
    for (int k = 0; k < 2; k++) {
        float4 t = w4g[tid + k * 512];
        t.x *= t.x; t.y *= t.y; t.z *= t.z; t.w *= t.w;
        ws4[tid + k * 512] = t;
    }
    if (tid < TT) sal[tid] = alphas[tid];
    __syncthreads();

    // 16 warps x 4 rows each: warp wid handles rows rl = wid*4 .. wid*4+3
    const float4* __restrict__ sal4 = reinterpret_cast<const float4*>(sal);
    #pragma unroll
    for (int rr = 0; rr < 4; rr++) {
        const int rl  = wid * 4 + rr;                 // 0..63 within group
        const int row = gi * NN + rl;
        const float4* __restrict__ g4 =
            reinterpret_cast<const float4*>(g + (size_t)row * GN);

        float acc0 = 0.f, acc1 = 0.f, acc2 = 0.f, acc3 = 0.f;
        #pragma unroll
        for (int c = 0; c < 8; c++) {
            const int base = c * 128 + lane;          // float4 units
            float4 a0 = g4[base];       float4 a1 = g4[base + 32];
            float4 a2 = g4[base + 64];  float4 a3 = g4[base + 96];
            float4 b0 = ws4[base];      float4 b1 = ws4[base + 32];
            float4 b2 = ws4[base + 64]; float4 b3 = ws4[base + 96];
            acc0 += dot4(a0, b0);
            acc1 += dot4(a1, b1);
            acc2 += dot4(a2, b2);
            acc3 += dot4(a3, b3);
        }
        float s = (acc0 + acc1) + (acc2 + acc3);
        #pragma unroll
        for (int o = 16; o > 0; o >>= 1)
            s += __shfl_xor_sync(0xffffffffu, s, o);  // all lanes get sum

        if (lane == 0) sv[rl] = s;                    // v stays in smem

        // F epilogue (vectorized, 42 STG.128)
        float4* __restrict__ Fr4 =
            reinterpret_cast<float4*>(Fout + (size_t)row * TT);
        #pragma unroll
        for (int t = lane; t < TT / 4; t += 32) {
            float4 a = sal4[t];
            a.x *= s; a.y *= s; a.z *= s; a.w *= s;
            Fr4[t] = a;
        }
    }

    // gate on y (finished ~6us ago; passes immediately, no parked time)
    __syncthreads();
    if (tid == 0) {
        while (ld_flag(&d_y_done) < Y_BLOCKS)
            __nanosleep(64);
        __threadfence();
    }
    __syncthreads();

    // Z column gi: thread (b = tid>>2, q = tid&3) does 16 j's, quad-reduce.
    {
        const int b = tid >> 2;              // 0..127
        const int q = tid & 3;               // 0..3
        const float4* __restrict__ y4 =
            reinterpret_cast<const float4*>(d_y + b * NN + q * 16);
        const float4* __restrict__ v4 =
            reinterpret_cast<const float4*>(sv + q * 16);

        float4 a0 = y4[0]; float4 a1 = y4[1]; float4 a2 = y4[2]; float4 a3 = y4[3];
        float s = dot4(a0, v4[0]) + dot4(a1, v4[1])
                + dot4(a2, v4[2]) + dot4(a3, v4[3]);
        s += __shfl_xor_sync(0xffffffffu, s, 1);
        s += __shfl_xor_sync(0xffffffffu, s, 2);
        if (q == 0)
            Zout[b * NN + gi] = s;           // plain store, unique writer
    }

    // last mv block resets counters for next graph replay (all gates passed)
    if (tid == 0) {
        if (atomicAdd(&d_mv_done, 1) == MV_BLOCKS - 1) {
            atomicExch(&d_mv_done, 0);
            atomicExch(&d_y_done, 0);
        }
    }
}

// ---------------------------------------------------------------------------
extern "C" void kernel_launch(void* const* d_in, const int* in_sizes, int n_in,
                              void* d_out, int out_size) {
    const float* x      = (const float*)d_in[0];   // [B, N, P]
    const int*   xi     = (const int*)  d_in[1];   // [B, P]
    const float* g      = (const float*)d_in[2];   // [N*N, N*N]
    const float* w      = (const float*)d_in[3];   // [N*N, 1]
    const float* alphas = (const float*)d_in[4];   // [1, T]

    float* out = (float*)d_out;
    float* Z = out;               // [B, N]   = 8192
    float* F = out + BB * NN;     // [N*N, T] = 688128

    k_all<<<TOTAL_BLK, THREADS>>>(g, w, alphas, x, xi, F, Z);
}

// round 15
// speedup vs baseline: 1.9850x; 1.9850x over previous
#include <cuda_runtime.h>

#define GN 4096   // N*N
#define TT 168    // T
#define BB 128    // B
#define NN 64     // N
#define PP 128    // P

#define ROWS_PER_BLK 16
#define MV_BLOCKS (GN / ROWS_PER_BLK)      // 256
#define YB_BATCH  4
#define Y_BLOCKS  (BB / YB_BATCH)          // 32
#define TOTAL_K1  (MV_BLOCKS + Y_BLOCKS)   // 288 blocks @ 512 thr (single wave)

#define F_ROWS_PER_BLK 16
#define F_BLOCKS  (GN / F_ROWS_PER_BLK)    // 256
#define TOTAL_K2  (F_BLOCKS + BB)          // 256 F-blocks + 128 Z-blocks = 384

#define TT4 (TT / 4)                       // 42 float4 per F row

// Scratch (allocation-free rule: __device__ globals)
__device__ float d_v[GN];
__device__ float d_y[BB * NN];

__device__ __forceinline__ float dot4(float4 a, float4 b) {
    return a.x * b.x + a.y * b.y + a.z * b.z + a.w * b.w;
}

// L1-bypass 128-bit load (g has zero reuse)
__device__ __forceinline__ float4 ldcg4(const float4* p) {
    float4 v;
    asm volatile("ld.global.cg.v4.f32 {%0,%1,%2,%3}, [%4];"
                 : "=f"(v.x), "=f"(v.y), "=f"(v.z), "=f"(v.w) : "l"(p));
    return v;
}

// ---------------------------------------------------------------------------
// Kernel 1 (512 threads; PURE compute, no F stores — stores moved to k2):
//  blocks [0, 256):  matvec, 16 rows/block, warp-per-row, w^2 staged in smem
//                    once per block. g via __ldcg. v -> d_v only.
//  blocks [256, 288): y for 4 batches: y[b,j] = sum_p x[b,j,p]*alpha[xi[b,p]].
// ---------------------------------------------------------------------------
__global__ void __launch_bounds__(512) k_main(const float* __restrict__ g,
                                              const float* __restrict__ w,
                                              const float* __restrict__ alphas,
                                              const float* __restrict__ x,
                                              const int*   __restrict__ xi) {
    __shared__ __align__(16) float ws[GN];     // matvec: w^2 | y-block: ap

    const int blk  = blockIdx.x;
    const int tid  = threadIdx.x;
    const int wid  = tid >> 5;
    const int lane = tid & 31;

    if (blk < MV_BLOCKS) {
        // ---- stage w^2 (16 KB) into smem ----
        const float4* __restrict__ w4g = reinterpret_cast<const float4*>(w);
        float4* ws4 = reinterpret_cast<float4*>(ws);
        #pragma unroll
        for (int k = 0; k < 2; k++) {
            float4 t = w4g[tid + k * 512];
            t.x *= t.x; t.y *= t.y; t.z *= t.z; t.w *= t.w;
            ws4[tid + k * 512] = t;
        }
        __syncthreads();

        // ---- warp-per-row dot product (row = blk*16 + wid) ----
        const int row = blk * ROWS_PER_BLK + wid;
        const float4* __restrict__ g4 =
            reinterpret_cast<const float4*>(g + (size_t)row * GN);

        float acc0 = 0.f, acc1 = 0.f, acc2 = 0.f, acc3 = 0.f;
        #pragma unroll
        for (int c = 0; c < 8; c++) {
            const int base = c * 128 + lane;          // float4 units
            float4 a0 = ldcg4(g4 + base);
            float4 a1 = ldcg4(g4 + base + 32);
            float4 a2 = ldcg4(g4 + base + 64);
            float4 a3 = ldcg4(g4 + base + 96);
            float4 b0 = ws4[base];      float4 b1 = ws4[base + 32];
            float4 b2 = ws4[base + 64]; float4 b3 = ws4[base + 96];
            acc0 += dot4(a0, b0);
            acc1 += dot4(a1, b1);
            acc2 += dot4(a2, b2);
            acc3 += dot4(a3, b3);
        }
        float s = (acc0 + acc1) + (acc2 + acc3);
        #pragma unroll
        for (int o = 16; o > 0; o >>= 1)
            s += __shfl_xor_sync(0xffffffffu, s, o);

        if (lane == 0) d_v[row] = s;
    } else {
        // ---- y-block: batches b0 .. b0+3 ----
        const int b0 = (blk - MV_BLOCKS) * YB_BATCH;
        float* ap = ws;   // 4 batches x 128 = 512 entries
        ap[tid] = alphas[xi[b0 * PP + tid]];
        __syncthreads();

        const int bsel = wid >> 2;           // 0..3
        const int b    = b0 + bsel;
        const int j00  = wid & 3;
        const float* __restrict__ apb = ap + bsel * PP;
        #pragma unroll
        for (int j = j00; j < NN; j += 4) {
            const float* __restrict__ xr = x + ((size_t)b * NN + j) * PP;
            float s = xr[lane]      * apb[lane]
                    + xr[lane + 32] * apb[lane + 32]
                    + xr[lane + 64] * apb[lane + 64]
                    + xr[lane + 96] * apb[lane + 96];
            #pragma unroll
            for (int o = 16; o > 0; o >>= 1)
                s += __shfl_xor_sync(0xffffffffu, s, o);
            if (lane == 0) d_y[b * NN + j] = s;
        }
    }
}

// ---------------------------------------------------------------------------
// Kernel 2 (F epilogue + Z, sharing one launch's fixed overhead):
//  blocks [0, 256):   F-block: rows r0=blk*16..+16. alphas + v slice staged
//                     in smem; warp w writes rows r0+w and r0+8+w
//                     (42 STG.128 per row). v is L2-hot from k_main.
//  blocks [256, 384): Z-block for batch b: Z[b,i] = sum_j v[i*64+j]*y[b,j].
//                     One output per 4-thread quad, 8 independent float4
//                     loads, 2 shfl reduce.
// ---------------------------------------------------------------------------
__global__ void __launch_bounds__(256) k_tail(const float* __restrict__ alphas,
                                              float* __restrict__ Fout,
                                              float* __restrict__ Zout) {
    const int blk = blockIdx.x;
    const int tid = threadIdx.x;

    if (blk < F_BLOCKS) {
        __shared__ __align__(16) float sal[TT + 8];
        __shared__ float sv[F_ROWS_PER_BLK];

        const int r0 = blk * F_ROWS_PER_BLK;
        if (tid < TT) sal[tid] = alphas[tid];
        if (tid < F_ROWS_PER_BLK) sv[tid] = d_v[r0 + tid];
        __syncthreads();

        const int wid  = tid >> 5;
        const int lane = tid & 31;
        const float4* __restrict__ sal4 = reinterpret_cast<const float4*>(sal);

        #pragma unroll
        for (int rr = 0; rr < 2; rr++) {
            const int rl  = wid + rr * 8;             // 0..15
            const float v = sv[rl];
            float4* __restrict__ Fr4 =
                reinterpret_cast<float4*>(Fout + (size_t)(r0 + rl) * TT);
            #pragma unroll
            for (int t = lane; t < TT4; t += 32) {
                float4 a = sal4[t];
                a.x *= v; a.y *= v; a.z *= v; a.w *= v;
                Fr4[t] = a;
            }
        }
    } else {
        const int b = blk - F_BLOCKS;
        const int i = tid >> 2;        // output row 0..63
        const int q = tid & 3;         // j-segment 0..3

        const float4* __restrict__ v4 =
            reinterpret_cast<const float4*>(d_v) + i * 16 + q * 4;
        const float4* __restrict__ y4 =
            reinterpret_cast<const float4*>(d_y) + b * 16 + q * 4;

        float4 a0 = v4[0]; float4 a1 = v4[1]; float4 a2 = v4[2]; float4 a3 = v4[3];
        float4 b0 = y4[0]; float4 b1 = y4[1]; float4 b2 = y4[2]; float4 b3 = y4[3];

        float s = (dot4(a0, b0) + dot4(a1, b1)) + (dot4(a2, b2) + dot4(a3, b3));
        s += __shfl_xor_sync(0xffffffffu, s, 1);
        s += __shfl_xor_sync(0xffffffffu, s, 2);

        if (q == 0)
            Zout[b * NN + i] = s;
    }
}

// ---------------------------------------------------------------------------
extern "C" void kernel_launch(void* const* d_in, const int* in_sizes, int n_in,
                              void* d_out, int out_size) {
    const float* x      = (const float*)d_in[0];   // [B, N, P]
    const int*   xi     = (const int*)  d_in[1];   // [B, P]
    const float* g      = (const float*)d_in[2];   // [N*N, N*N]
    const float* w      = (const float*)d_in[3];   // [N*N, 1]
    const float* alphas = (const float*)d_in[4];   // [1, T]

    float* out = (float*)d_out;
    float* Z = out;               // [B, N]   = 8192
    float* F = out + BB * NN;     // [N*N, T] = 688128

    k_main<<<TOTAL_K1, 512>>>(g, w, alphas, x, xi);
    k_tail<<<TOTAL_K2, 256>>>(alphas, F, Z);
}